// round 9
// baseline (speedup 1.0000x reference)
#include <cuda_runtime.h>

#define BATCH 8
#define NPTS 2048
#define DIM 32
#define KNN 16
#define NTOT (BATCH*NPTS)          /* 16384 */
#define YOFF (NTOT*DIM)            /* 524288 */

#define KNN_BLOCKS (NTOT/16)       /* 1024: 16 queries/block, 2 per warp */
#define FEAT_BLOCKS (NTOT/32)      /* 512: 32 points/block */

typedef unsigned long long u64;

// -------- scratch (device globals: no allocation allowed) --------
__device__ float g_xA[NTOT*DIM];
__device__ float g_xB[NTOT*DIM];
__device__ float g_xC[NTOT*DIM];
__device__ int   g_idx[NTOT*KNN];

// -------- packed f32x2 helpers (sm_100a PTX) --------
#define PACK2(d, lo, hi) \
    asm("mov.b64 %0, {%1, %2};" : "=l"(d) : "r"(__float_as_uint(lo)), "r"(__float_as_uint(hi)))
#define UNPACK2(lo, hi, s) do { unsigned _ulo, _uhi; \
    asm("mov.b64 {%0, %1}, %2;" : "=r"(_ulo), "=r"(_uhi) : "l"(s)); \
    lo = __uint_as_float(_ulo); hi = __uint_as_float(_uhi); } while(0)
#define FMA2(acc, a, b) \
    asm("fma.rn.f32x2 %0, %1, %2, %0;" : "+l"(acc) : "l"(a), "l"(b))
#define ADD2(d, a, b) \
    asm("add.rn.f32x2 %0, %1, %2;" : "=l"(d) : "l"(a), "l"(b))
#define SUB2(d, a, b) \
    asm("sub.rn.f32x2 %0, %1, %2;" : "=l"(d) : "l"(a), "l"(b))

// u64 key = (dist_bits << 32) | index, built in one mov.b64
#define MAKEKEY(key, dbits, j) \
    asm("mov.b64 %0, {%1, %2};" : "=l"(key) : "r"(j), "r"(dbits))

// Exact (non-FMA-contracted) squared distance, matching XLA's
// mul/mul/mul + sequential-add lowering of sum((pi-pj)**2, -1).
__device__ __forceinline__ float sqdist_exact(float dx, float dy, float dz) {
    return __fadd_rn(__fadd_rn(__fmul_rn(dx, dx), __fmul_rn(dy, dy)),
                     __fmul_rn(dz, dz));
}

#define INFKEY 0xffffffffffffffffULL

__device__ __forceinline__ void ins3u(u64 k, u64& k0, u64& k1, u64& k2) {
    if (k < k2) {
        if (k < k1) {
            k2 = k1;
            if (k < k0) { k1 = k0; k0 = k; }
            else        { k1 = k; }
        } else k2 = k;
    }
}

// ============================================================
// Kernel 1 (fused): blocks [0, KNN_BLOCKS) do 16-NN (2 queries/warp);
// blocks [KNN_BLOCKS, +FEAT_BLOCKS) do the 3 feature GEMVs + p passthrough.
// ============================================================
__global__ void __launch_bounds__(256, 4) prep_kernel(const float* __restrict__ x,
                                                      const float* __restrict__ p,
                                                      const float* __restrict__ Aw,
                                                      const float* __restrict__ Ab,
                                                      const float* __restrict__ Bw,
                                                      const float* __restrict__ Bb,
                                                      const float* __restrict__ Cw,
                                                      const float* __restrict__ Cb,
                                                      float* __restrict__ out) {
    __shared__ __align__(16) float smx[NPTS];
    __shared__ __align__(16) float smy[NPTS];
    __shared__ __align__(16) float smz[NPTS];
    int tid = threadIdx.x;
    int warp = tid >> 5, lane = tid & 31;

    if (blockIdx.x < KNN_BLOCKS) {
        // ------- KNN branch: 2 queries per warp, SoA tile, redux pops -------
        int b = blockIdx.x >> 7;                 // 128 blocks per batch
        int qbase = (blockIdx.x & 127) << 4;     // 16 queries per block
        const float* pb = p + b * NPTS * 3;

        for (int u = tid; u < NPTS; u += 256) {
            smx[u] = pb[3*u];
            smy[u] = pb[3*u + 1];
            smz[u] = pb[3*u + 2];
        }
        __syncthreads();

        int qA = qbase + warp * 2, qB = qA + 1;
        float qax = smx[qA], qay = smy[qA], qaz = smz[qA];
        float qbx = smx[qB], qby = smy[qB], qbz = smz[qB];

        u64 a0 = INFKEY, a1 = INFKEY, a2 = INFKEY;
        u64 b0 = INFKEY, b1 = INFKEY, b2 = INFKEY;
#pragma unroll 4
        for (int t = 0; t < 64; t++) {
            int j = lane + (t << 5);
            float cx = smx[j], cy = smy[j], cz = smz[j];
            float da = sqdist_exact(qax - cx, qay - cy, qaz - cz);
            float db = sqdist_exact(qbx - cx, qby - cy, qbz - cz);
            u64 ka; MAKEKEY(ka, __float_as_uint(da), j);
            u64 kb; MAKEKEY(kb, __float_as_uint(db), j);
            ins3u(ka, a0, a1, a2);
            ins3u(kb, b0, b1, b2);
        }

        u64 lpA = 0, lpB = 0;
        int myjA = 0, myjB = 0;

        for (int r = 0; r < KNN + 1; r++) {
            // --- pop query A and query B, chains interleaved ---
            unsigned dminA = __reduce_min_sync(0xffffffffu, (unsigned)(a0 >> 32));
            unsigned dminB = __reduce_min_sync(0xffffffffu, (unsigned)(b0 >> 32));
            unsigned jcA = ((unsigned)(a0 >> 32) == dminA) ? (unsigned)a0 : 0xffffffffu;
            unsigned jcB = ((unsigned)(b0 >> 32) == dminB) ? (unsigned)b0 : 0xffffffffu;
            unsigned jminA = __reduce_min_sync(0xffffffffu, jcA);
            unsigned jminB = __reduce_min_sync(0xffffffffu, jcB);
            u64 bkA; MAKEKEY(bkA, dminA, jminA);
            u64 bkB; MAKEKEY(bkB, dminB, jminB);

            if (lane == r - 1) { myjA = (int)jminA; myjB = (int)jminB; }

            if (a0 == bkA) {
                lpA = a0;
                a0 = a1; a1 = a2; a2 = INFKEY;
                if (a0 == INFKEY) {
                    for (int t = 0; t < 64; t++) {
                        int j = lane + (t << 5);
                        float da = sqdist_exact(qax - smx[j], qay - smy[j], qaz - smz[j]);
                        u64 key; MAKEKEY(key, __float_as_uint(da), j);
                        if (key > lpA) ins3u(key, a0, a1, a2);
                    }
                }
            }
            if (b0 == bkB) {
                lpB = b0;
                b0 = b1; b1 = b2; b2 = INFKEY;
                if (b0 == INFKEY) {
                    for (int t = 0; t < 64; t++) {
                        int j = lane + (t << 5);
                        float db = sqdist_exact(qbx - smx[j], qby - smy[j], qbz - smz[j]);
                        u64 key; MAKEKEY(key, __float_as_uint(db), j);
                        if (key > lpB) ins3u(key, b0, b1, b2);
                    }
                }
            }
        }
        if (lane < KNN) {
            g_idx[(b * NPTS + qA) * KNN + lane] = myjA;
            g_idx[(b * NPTS + qB) * KNN + lane] = myjB;
        }
    } else {
        // ---------------- FEAT branch: warp-per-point (4 pts/warp) ----------------
        float* sAw = smx;                  // 1024 floats
        float* sBw = smy;                  // 1024
        float* sCw = smz;                  // 1024
        float* sAb = smx + 1024;           // 32
        float* sBb = smy + 1024;           // 32
        float* sCb = smz + 1024;           // 32

        for (int u = tid; u < 1024; u += 256) {
            sAw[u] = Aw[u]; sBw[u] = Bw[u]; sCw[u] = Cw[u];
        }
        if (tid < 32) { sAb[tid] = Ab[tid]; sBb[tid] = Bb[tid]; sCb[tid] = Cb[tid]; }
        __syncthreads();

        int fb = blockIdx.x - KNN_BLOCKS;
        int pt0 = fb * 32 + warp * 4;
#pragma unroll
        for (int q = 0; q < 4; q++) {
            int pt = pt0 + q;
            float xv = x[pt * DIM + lane];
            float a = sAb[lane], bb = sBb[lane], cc = sCb[lane];
#pragma unroll
            for (int d = 0; d < 32; d++) {
                float xd = __shfl_sync(0xffffffffu, xv, d);
                a  = fmaf(xd, sAw[d*32 + lane], a);
                bb = fmaf(xd, sBw[d*32 + lane], bb);
                cc = fmaf(xd, sCw[d*32 + lane], cc);
            }
            g_xA[pt*DIM + lane] = a;
            g_xB[pt*DIM + lane] = bb;
            g_xC[pt*DIM + lane] = cc;
        }
        // p passthrough -> second part of output (96 floats per feat block)
        if (tid < 96) out[YOFF + fb*96 + tid] = p[fb*96 + tid];
    }
}

// ============================================================
// Kernel 2: fused gather + position MLP + value MLP + softmax + y.
// 128 threads = 8 points x 16 neighbors, one pair per thread.
// smem-staged h2/val, two-pass softmax. Pad-33 rows -> 5 blocks/SM.
// ============================================================
__global__ void __launch_bounds__(128, 5) attn_kernel(const float* __restrict__ p,
                                                      const float* __restrict__ pm1w,
                                                      const float* __restrict__ pm1b,
                                                      const float* __restrict__ pm2w,
                                                      const float* __restrict__ pm2b,
                                                      const float* __restrict__ vm1w,
                                                      const float* __restrict__ vm1b,
                                                      const float* __restrict__ vm2w,
                                                      const float* __restrict__ vm2b,
                                                      float* __restrict__ out) {
    __shared__ __align__(16) float s_pm1w[192];
    __shared__ __align__(16) float s_pm1b[64];
    __shared__ __align__(16) float s_pm2w[2048];
    __shared__ __align__(16) float s_pm2b[32];
    __shared__ __align__(16) float s_vm1t[128];   // transposed: [jj][c]
    __shared__ __align__(16) float s_vm1b[4];
    __shared__ __align__(16) float s_vm2w[128];   // [jj][c]
    __shared__ __align__(16) float s_vm2b[32];
    __shared__ __align__(16) float s_xi[8][32];
    __shared__ __align__(16) float s_h2[8][16][33];
    __shared__ __align__(16) float s_val[8][16][33];

    int tid = threadIdx.x;
    int gp0 = blockIdx.x << 3;

    // ---- load weights + x_i tile ----
    for (int u = tid; u < 2048; u += 128) s_pm2w[u] = pm2w[u];
    for (int u = tid; u < 192;  u += 128) s_pm1w[u] = pm1w[u];
    if (tid < 64)  s_pm1b[tid] = pm1b[tid];
    if (tid < 32)  { s_pm2b[tid] = pm2b[tid]; s_vm2b[tid] = vm2b[tid]; }
    if (tid < 128) {
        int c = tid >> 2, jj = tid & 3;           // vm1w is [c][jj]
        s_vm1t[jj*32 + c] = vm1w[tid];
        s_vm2w[tid] = vm2w[tid];                  // already [jj][c]
    }
    if (tid < 4) s_vm1b[tid] = vm1b[tid];
    for (int u = tid; u < 256; u += 128)
        s_xi[u >> 5][u & 31] = g_xA[(gp0 << 5) + u];
    __syncthreads();

    int pt = tid >> 4, k = tid & 15;
    int gp = gp0 + pt;
    int b = gp >> 11, ii = gp & 2047;
    int j = g_idx[(gp << 4) + k];

    const float* pb = p + b * NPTS * 3;
    float dx = pb[ii*3 + 0] - pb[j*3 + 0];
    float dy = pb[ii*3 + 1] - pb[j*3 + 1];
    float dz = pb[ii*3 + 2] - pb[j*3 + 2];

    // ---- posi_diff MLP: 3 -> 64 (relu) -> 32, packed accumulators ----
    u64 pd2[16];
#pragma unroll
    for (int i = 0; i < 16; i++)
        pd2[i] = *(const u64*)&s_pm2b[2*i];

#pragma unroll
    for (int ch = 0; ch < 4; ch++) {
        float h1c[16];
#pragma unroll
        for (int m = 0; m < 16; m++) {
            int mg = (ch << 4) + m;
            float v = s_pm1b[mg];
            v = fmaf(dx, s_pm1w[mg],       v);
            v = fmaf(dy, s_pm1w[64 + mg],  v);
            v = fmaf(dz, s_pm1w[128 + mg], v);
            h1c[m] = fmaxf(v, 0.0f);
        }
#pragma unroll
        for (int m = 0; m < 16; m++) {
            int mg = (ch << 4) + m;
            u64 hp; PACK2(hp, h1c[m], h1c[m]);
            const ulonglong2* wr = (const ulonglong2*)&s_pm2w[mg * 32];
#pragma unroll
            for (int i = 0; i < 8; i++) {
                ulonglong2 w = wr[i];                  // LDS.128 = 2 weight pairs
                FMA2(pd2[2*i],     hp, w.x);
                FMA2(pd2[2*i + 1], hp, w.y);
            }
        }
    }

    // ---- gather neighbor rows; h = xi - xB + pd ; vm1 ; val -> smem ----
    int row = (b << 11) + j;
    const float4* xb4 = (const float4*)(g_xB + (row << 5));
    const float4* xc4 = (const float4*)(g_xC + (row << 5));

    u64 acc2[4] = {0ull, 0ull, 0ull, 0ull};
#pragma unroll
    for (int q = 0; q < 8; q++) {
        float4 vb = xb4[q];
        float4 vc = xc4[q];
#pragma unroll
        for (int half = 0; half < 2; half++) {
            int pi = 2*q + half;
            int c0 = 4*q + 2*half;
            u64 xbp, xcp;
            if (half == 0) { PACK2(xbp, vb.x, vb.y); PACK2(xcp, vc.x, vc.y); }
            else           { PACK2(xbp, vb.z, vb.w); PACK2(xcp, vc.z, vc.w); }
            u64 xip = *(const u64*)&s_xi[pt][c0];
            u64 t, hpair;
            SUB2(t, xip, xbp);
            ADD2(hpair, t, pd2[pi]);
#pragma unroll
            for (int jj = 0; jj < 4; jj++)
                FMA2(acc2[jj], hpair, *(const u64*)&s_vm1t[jj*32 + c0]);
            u64 valp;
            ADD2(valp, pd2[pi], xcp);
            float vlo, vhi; UNPACK2(vlo, vhi, valp);
            s_val[pt][k][c0]     = vlo;
            s_val[pt][k][c0 + 1] = vhi;
        }
    }

    float hv[4];
#pragma unroll
    for (int jj = 0; jj < 4; jj++) {
        float lo, hi; UNPACK2(lo, hi, acc2[jj]);
        hv[jj] = fmaxf(lo + hi + s_vm1b[jj], 0.0f);
    }

    // ---- vm2: h2 = vm2b + hv @ vm2w  (packed over c-pairs) ----
    u64 hvp[4];
#pragma unroll
    for (int jj = 0; jj < 4; jj++) PACK2(hvp[jj], hv[jj], hv[jj]);
#pragma unroll
    for (int pi = 0; pi < 16; pi++) {
        int c0 = 2*pi;
        u64 h2p = *(const u64*)&s_vm2b[c0];
#pragma unroll
        for (int jj = 0; jj < 4; jj++)
            FMA2(h2p, hvp[jj], *(const u64*)&s_vm2w[jj*32 + c0]);
        float hlo, hhi; UNPACK2(hlo, hhi, h2p);
        s_h2[pt][k][c0]     = hlo;
        s_h2[pt][k][c0 + 1] = hhi;
    }
    __syncthreads();

    // ---- softmax over k per (pt, c) + weighted sum ----
    for (int task = tid; task < 256; task += 128) {
        int tp = task >> 5, c = task & 31;
        float m = s_h2[tp][0][c];
#pragma unroll
        for (int kk = 1; kk < 16; kk++) m = fmaxf(m, s_h2[tp][kk][c]);
        float s = 0.0f, acc = 0.0f;
#pragma unroll
        for (int kk = 0; kk < 16; kk++) {
            float e = __expf(s_h2[tp][kk][c] - m);
            s += e;
            acc = fmaf(e, s_val[tp][kk][c], acc);
        }
        out[((gp0 + tp) << 5) + c] = acc / s;
    }
}

// ============================================================
extern "C" void kernel_launch(void* const* d_in, const int* in_sizes, int n_in,
                              void* d_out, int out_size) {
    const float* x = (const float*)d_in[0];
    const float* p = (const float*)d_in[1];

    prep_kernel<<<KNN_BLOCKS + FEAT_BLOCKS, 256>>>(
        x, p,
        (const float*)d_in[2], (const float*)d_in[3],
        (const float*)d_in[4], (const float*)d_in[5],
        (const float*)d_in[6], (const float*)d_in[7],
        (float*)d_out);

    attn_kernel<<<NTOT/8, 128>>>(
        p,
        (const float*)d_in[8],  (const float*)d_in[9],
        (const float*)d_in[10], (const float*)d_in[11],
        (const float*)d_in[12], (const float*)d_in[13],
        (const float*)d_in[14], (const float*)d_in[15],
        (float*)d_out);
}

// round 11
// speedup vs baseline: 1.0655x; 1.0655x over previous
#include <cuda_runtime.h>

#define BATCH 8
#define NPTS 2048
#define DIM 32
#define KNN 16
#define NTOT (BATCH*NPTS)          /* 16384 */
#define YOFF (NTOT*DIM)            /* 524288 */

#define KNN_BLOCKS (NTOT/8)        /* 2048: 8 queries/block, warp per query */
#define FEAT_BLOCKS (NTOT/32)      /* 512: 32 points/block */

typedef unsigned long long u64;

// -------- scratch (device globals: no allocation allowed) --------
__device__ float g_xA[NTOT*DIM];
__device__ float g_xB[NTOT*DIM];
__device__ float g_xC[NTOT*DIM];
__device__ int   g_idx[NTOT*KNN];

// -------- packed f32x2 helpers (sm_100a PTX) --------
#define PACK2(d, lo, hi) \
    asm("mov.b64 %0, {%1, %2};" : "=l"(d) : "r"(__float_as_uint(lo)), "r"(__float_as_uint(hi)))
#define UNPACK2(lo, hi, s) do { unsigned _ulo, _uhi; \
    asm("mov.b64 {%0, %1}, %2;" : "=r"(_ulo), "=r"(_uhi) : "l"(s)); \
    lo = __uint_as_float(_ulo); hi = __uint_as_float(_uhi); } while(0)
#define FMA2(acc, a, b) \
    asm("fma.rn.f32x2 %0, %1, %2, %0;" : "+l"(acc) : "l"(a), "l"(b))
#define ADD2(d, a, b) \
    asm("add.rn.f32x2 %0, %1, %2;" : "=l"(d) : "l"(a), "l"(b))
#define SUB2(d, a, b) \
    asm("sub.rn.f32x2 %0, %1, %2;" : "=l"(d) : "l"(a), "l"(b))

// Exact (non-FMA-contracted) squared distance, matching XLA's
// mul/mul/mul + sequential-add lowering of sum((pi-pj)**2, -1).
__device__ __forceinline__ float sqdist_exact(float dx, float dy, float dz) {
    return __fadd_rn(__fadd_rn(__fmul_rn(dx, dx), __fmul_rn(dy, dy)),
                     __fmul_rn(dz, dz));
}

#define INF_F  __int_as_float(0x7f800000)
#define IMAXS  0x7fffffff

// float-key top-3 insert. Candidates arrive with strictly increasing j,
// so strict '<' keeps the smaller index on exact distance ties — identical
// ordering to the u64 (dist,idx) key. FSETP-based: ~half the SASS of u64.
__device__ __forceinline__ void ins3f(float d, int j,
                                      float& d0, int& i0,
                                      float& d1, int& i1,
                                      float& d2, int& i2) {
    if (d < d2) {
        if (d < d1) {
            d2 = d1; i2 = i1;
            if (d < d0) { d1 = d0; i1 = i0; d0 = d; i0 = j; }
            else        { d1 = d;  i1 = j; }
        } else { d2 = d; i2 = j; }
    }
}

// ============================================================
// Kernel 1 (fused): blocks [0, KNN_BLOCKS) do 16-NN (warp/query);
// blocks [KNN_BLOCKS, +FEAT_BLOCKS) do the 3 feature GEMVs + p passthrough.
// ============================================================
__global__ void __launch_bounds__(256, 5) prep_kernel(const float* __restrict__ x,
                                                      const float* __restrict__ p,
                                                      const float* __restrict__ Aw,
                                                      const float* __restrict__ Ab,
                                                      const float* __restrict__ Bw,
                                                      const float* __restrict__ Bb,
                                                      const float* __restrict__ Cw,
                                                      const float* __restrict__ Cb,
                                                      float* __restrict__ out) {
    __shared__ __align__(16) float4 sm4[NPTS];   // 32KB
    int tid = threadIdx.x;
    int warp = tid >> 5, lane = tid & 31;

    if (blockIdx.x < KNN_BLOCKS) {
        // ------- KNN branch: warp-per-query, float keys, redux pops -------
        int b = blockIdx.x >> 8;                 // 256 blocks per batch
        int qbase = (blockIdx.x & 255) << 3;     // 8 queries per block
        const float* pb = p + b * NPTS * 3;

        for (int u = tid; u < NPTS; u += 256)
            sm4[u] = make_float4(pb[3*u], pb[3*u+1], pb[3*u+2], 0.0f);
        __syncthreads();

        int qi = qbase + warp;
        float4 q4 = sm4[qi];

        float d0 = INF_F, d1 = INF_F, d2 = INF_F;
        int   i0 = IMAXS, i1 = IMAXS, i2 = IMAXS;
#pragma unroll 4
        for (int t = 0; t < 64; t++) {
            int j = lane + (t << 5);
            float4 c4 = sm4[j];
            float d = sqdist_exact(q4.x - c4.x, q4.y - c4.y, q4.z - c4.z);
            ins3f(d, j, d0, i0, d1, i1, d2, i2);
        }

        unsigned lpd = 0; int lpj = -1;   // last popped (dist bits, idx)
        int myj = 0;                       // this lane's buffered output index

        for (int r = 0; r < KNN + 1; r++) {
            // global min = (min dist bits, then min index among that dist).
            // dist >= 0 so float order == uint order on the bits.
            unsigned myd = __float_as_uint(d0);
            unsigned dmin = __reduce_min_sync(0xffffffffu, myd);
            unsigned jc = (myd == dmin) ? (unsigned)i0 : 0xffffffffu;
            unsigned jmin = __reduce_min_sync(0xffffffffu, jc);

            if (lane == r - 1) myj = (int)jmin;  // round 0 == self, dropped

            if (myd == dmin && (unsigned)i0 == jmin) {   // unique winner lane
                lpd = dmin; lpj = (int)jmin;
                d0 = d1; i0 = i1; d1 = d2; i1 = i2; d2 = INF_F; i2 = IMAXS;
                if (i0 == IMAXS) {
                    // refill with 3 smallest keys strictly greater than (lpd,lpj)
                    for (int t = 0; t < 64; t++) {
                        int j = lane + (t << 5);
                        float4 c4 = sm4[j];
                        float d = sqdist_exact(q4.x - c4.x, q4.y - c4.y, q4.z - c4.z);
                        unsigned db = __float_as_uint(d);
                        if (db > lpd || (db == lpd && j > lpj))
                            ins3f(d, j, d0, i0, d1, i1, d2, i2);
                    }
                }
            }
        }
        if (lane < KNN)
            g_idx[(b * NPTS + qi) * KNN + lane] = myj;   // coalesced
    } else {
        // ---------------- FEAT branch: warp-per-point (4 pts/warp) ----------------
        float* sm = (float*)sm4;
        float* sAw = sm;            // 1024
        float* sBw = sm + 1024;     // 1024
        float* sCw = sm + 2048;     // 1024
        float* sAb = sm + 3072;     // 32
        float* sBb = sm + 3104;     // 32
        float* sCb = sm + 3136;     // 32

        for (int u = tid; u < 1024; u += 256) {
            sAw[u] = Aw[u]; sBw[u] = Bw[u]; sCw[u] = Cw[u];
        }
        if (tid < 32) { sAb[tid] = Ab[tid]; sBb[tid] = Bb[tid]; sCb[tid] = Cb[tid]; }
        __syncthreads();

        int fb = blockIdx.x - KNN_BLOCKS;
        int pt0 = fb * 32 + warp * 4;
#pragma unroll
        for (int q = 0; q < 4; q++) {
            int pt = pt0 + q;
            float xv = x[pt * DIM + lane];
            float a = sAb[lane], bb = sBb[lane], cc = sCb[lane];
#pragma unroll
            for (int d = 0; d < 32; d++) {
                float xd = __shfl_sync(0xffffffffu, xv, d);
                a  = fmaf(xd, sAw[d*32 + lane], a);
                bb = fmaf(xd, sBw[d*32 + lane], bb);
                cc = fmaf(xd, sCw[d*32 + lane], cc);
            }
            g_xA[pt*DIM + lane] = a;
            g_xB[pt*DIM + lane] = bb;
            g_xC[pt*DIM + lane] = cc;
        }
        // p passthrough -> second part of output (96 floats per feat block)
        if (tid < 96) out[YOFF + fb*96 + tid] = p[fb*96 + tid];
    }
}

// ============================================================
// Kernel 2: fused gather + position MLP + value MLP + softmax + y.
// 128 threads = 8 points x 16 neighbors, one pair per thread.
// smem-staged h2/val, two-pass softmax. Pad-33 rows -> 5 blocks/SM.
// ============================================================
__global__ void __launch_bounds__(128, 5) attn_kernel(const float* __restrict__ p,
                                                      const float* __restrict__ pm1w,
                                                      const float* __restrict__ pm1b,
                                                      const float* __restrict__ pm2w,
                                                      const float* __restrict__ pm2b,
                                                      const float* __restrict__ vm1w,
                                                      const float* __restrict__ vm1b,
                                                      const float* __restrict__ vm2w,
                                                      const float* __restrict__ vm2b,
                                                      float* __restrict__ out) {
    __shared__ __align__(16) float s_pm1w[192];
    __shared__ __align__(16) float s_pm1b[64];
    __shared__ __align__(16) float s_pm2w[2048];
    __shared__ __align__(16) float s_pm2b[32];
    __shared__ __align__(16) float s_vm1t[128];   // transposed: [jj][c]
    __shared__ __align__(16) float s_vm1b[4];
    __shared__ __align__(16) float s_vm2w[128];   // [jj][c]
    __shared__ __align__(16) float s_vm2b[32];
    __shared__ __align__(16) float s_xi[8][32];
    __shared__ __align__(16) float s_h2[8][16][33];
    __shared__ __align__(16) float s_val[8][16][33];

    int tid = threadIdx.x;
    int gp0 = blockIdx.x << 3;

    // ---- load weights + x_i tile ----
    for (int u = tid; u < 2048; u += 128) s_pm2w[u] = pm2w[u];
    for (int u = tid; u < 192;  u += 128) s_pm1w[u] = pm1w[u];
    if (tid < 64)  s_pm1b[tid] = pm1b[tid];
    if (tid < 32)  { s_pm2b[tid] = pm2b[tid]; s_vm2b[tid] = vm2b[tid]; }
    if (tid < 128) {
        int c = tid >> 2, jj = tid & 3;           // vm1w is [c][jj]
        s_vm1t[jj*32 + c] = vm1w[tid];
        s_vm2w[tid] = vm2w[tid];                  // already [jj][c]
    }
    if (tid < 4) s_vm1b[tid] = vm1b[tid];
    for (int u = tid; u < 256; u += 128)
        s_xi[u >> 5][u & 31] = g_xA[(gp0 << 5) + u];
    __syncthreads();

    int pt = tid >> 4, k = tid & 15;
    int gp = gp0 + pt;
    int b = gp >> 11, ii = gp & 2047;
    int j = g_idx[(gp << 4) + k];

    const float* pb = p + b * NPTS * 3;
    float dx = pb[ii*3 + 0] - pb[j*3 + 0];
    float dy = pb[ii*3 + 1] - pb[j*3 + 1];
    float dz = pb[ii*3 + 2] - pb[j*3 + 2];

    // ---- posi_diff MLP: 3 -> 64 (relu) -> 32, packed accumulators ----
    u64 pd2[16];
#pragma unroll
    for (int i = 0; i < 16; i++)
        pd2[i] = *(const u64*)&s_pm2b[2*i];

#pragma unroll
    for (int ch = 0; ch < 4; ch++) {
        float h1c[16];
#pragma unroll
        for (int m = 0; m < 16; m++) {
            int mg = (ch << 4) + m;
            float v = s_pm1b[mg];
            v = fmaf(dx, s_pm1w[mg],       v);
            v = fmaf(dy, s_pm1w[64 + mg],  v);
            v = fmaf(dz, s_pm1w[128 + mg], v);
            h1c[m] = fmaxf(v, 0.0f);
        }
#pragma unroll
        for (int m = 0; m < 16; m++) {
            int mg = (ch << 4) + m;
            u64 hp; PACK2(hp, h1c[m], h1c[m]);
            const ulonglong2* wr = (const ulonglong2*)&s_pm2w[mg * 32];
#pragma unroll
            for (int i = 0; i < 8; i++) {
                ulonglong2 w = wr[i];                  // LDS.128 = 2 weight pairs
                FMA2(pd2[2*i],     hp, w.x);
                FMA2(pd2[2*i + 1], hp, w.y);
            }
        }
    }

    // ---- gather neighbor rows; h = xi - xB + pd ; vm1 ; val -> smem ----
    int row = (b << 11) + j;
    const float4* xb4 = (const float4*)(g_xB + (row << 5));
    const float4* xc4 = (const float4*)(g_xC + (row << 5));

    u64 acc2[4] = {0ull, 0ull, 0ull, 0ull};
#pragma unroll
    for (int q = 0; q < 8; q++) {
        float4 vb = xb4[q];
        float4 vc = xc4[q];
#pragma unroll
        for (int half = 0; half < 2; half++) {
            int pi = 2*q + half;
            int c0 = 4*q + 2*half;
            u64 xbp, xcp;
            if (half == 0) { PACK2(xbp, vb.x, vb.y); PACK2(xcp, vc.x, vc.y); }
            else           { PACK2(xbp, vb.z, vb.w); PACK2(xcp, vc.z, vc.w); }
            u64 xip = *(const u64*)&s_xi[pt][c0];
            u64 t, hpair;
            SUB2(t, xip, xbp);
            ADD2(hpair, t, pd2[pi]);
#pragma unroll
            for (int jj = 0; jj < 4; jj++)
                FMA2(acc2[jj], hpair, *(const u64*)&s_vm1t[jj*32 + c0]);
            u64 valp;
            ADD2(valp, pd2[pi], xcp);
            float vlo, vhi; UNPACK2(vlo, vhi, valp);
            s_val[pt][k][c0]     = vlo;
            s_val[pt][k][c0 + 1] = vhi;
        }
    }

    float hv[4];
#pragma unroll
    for (int jj = 0; jj < 4; jj++) {
        float lo, hi; UNPACK2(lo, hi, acc2[jj]);
        hv[jj] = fmaxf(lo + hi + s_vm1b[jj], 0.0f);
    }

    // ---- vm2: h2 = vm2b + hv @ vm2w  (packed over c-pairs) ----
    u64 hvp[4];
#pragma unroll
    for (int jj = 0; jj < 4; jj++) PACK2(hvp[jj], hv[jj], hv[jj]);
#pragma unroll
    for (int pi = 0; pi < 16; pi++) {
        int c0 = 2*pi;
        u64 h2p = *(const u64*)&s_vm2b[c0];
#pragma unroll
        for (int jj = 0; jj < 4; jj++)
            FMA2(h2p, hvp[jj], *(const u64*)&s_vm2w[jj*32 + c0]);
        float hlo, hhi; UNPACK2(hlo, hhi, h2p);
        s_h2[pt][k][c0]     = hlo;
        s_h2[pt][k][c0 + 1] = hhi;
    }
    __syncthreads();

    // ---- softmax over k per (pt, c) + weighted sum ----
    for (int task = tid; task < 256; task += 128) {
        int tp = task >> 5, c = task & 31;
        float m = s_h2[tp][0][c];
#pragma unroll
        for (int kk = 1; kk < 16; kk++) m = fmaxf(m, s_h2[tp][kk][c]);
        float s = 0.0f, acc = 0.0f;
#pragma unroll
        for (int kk = 0; kk < 16; kk++) {
            float e = __expf(s_h2[tp][kk][c] - m);
            s += e;
            acc = fmaf(e, s_val[tp][kk][c], acc);
        }
        out[((gp0 + tp) << 5) + c] = acc / s;
    }
}

// ============================================================
extern "C" void kernel_launch(void* const* d_in, const int* in_sizes, int n_in,
                              void* d_out, int out_size) {
    const float* x = (const float*)d_in[0];
    const float* p = (const float*)d_in[1];

    prep_kernel<<<KNN_BLOCKS + FEAT_BLOCKS, 256>>>(
        x, p,
        (const float*)d_in[2], (const float*)d_in[3],
        (const float*)d_in[4], (const float*)d_in[5],
        (const float*)d_in[6], (const float*)d_in[7],
        (float*)d_out);

    attn_kernel<<<NTOT/8, 128>>>(
        p,
        (const float*)d_in[8],  (const float*)d_in[9],
        (const float*)d_in[10], (const float*)d_in[11],
        (const float*)d_in[12], (const float*)d_in[13],
        (const float*)d_in[14], (const float*)d_in[15],
        (float*)d_out);
}

// round 14
// speedup vs baseline: 1.1169x; 1.0482x over previous
#include <cuda_runtime.h>

#define BATCH 8
#define NPTS 2048
#define DIM 32
#define KNN 16
#define NTOT (BATCH*NPTS)          /* 16384 */
#define YOFF (NTOT*DIM)            /* 524288 */

#define KNN_BLOCKS (NTOT/8)        /* 2048: 8 queries/block, warp per query */
#define FEAT_BLOCKS (NTOT/32)      /* 512: 32 points/block */

typedef unsigned long long u64;

// -------- scratch (device globals: no allocation allowed) --------
__device__ float g_xA[NTOT*DIM];
__device__ float g_xB[NTOT*DIM];
__device__ float g_xC[NTOT*DIM];
__device__ int   g_idx[NTOT*KNN];

// -------- packed f32x2 helpers (sm_100a PTX) --------
#define PACK2(d, lo, hi) \
    asm("mov.b64 %0, {%1, %2};" : "=l"(d) : "r"(__float_as_uint(lo)), "r"(__float_as_uint(hi)))
#define UNPACK2(lo, hi, s) do { unsigned _ulo, _uhi; \
    asm("mov.b64 {%0, %1}, %2;" : "=r"(_ulo), "=r"(_uhi) : "l"(s)); \
    lo = __uint_as_float(_ulo); hi = __uint_as_float(_uhi); } while(0)
#define FMA2(acc, a, b) \
    asm("fma.rn.f32x2 %0, %1, %2, %0;" : "+l"(acc) : "l"(a), "l"(b))
#define ADD2(d, a, b) \
    asm("add.rn.f32x2 %0, %1, %2;" : "=l"(d) : "l"(a), "l"(b))
#define SUB2(d, a, b) \
    asm("sub.rn.f32x2 %0, %1, %2;" : "=l"(d) : "l"(a), "l"(b))

// Exact (non-FMA-contracted) squared distance, matching XLA's
// mul/mul/mul + sequential-add lowering of sum((pi-pj)**2, -1).
__device__ __forceinline__ float sqdist_exact(float dx, float dy, float dz) {
    return __fadd_rn(__fadd_rn(__fmul_rn(dx, dx), __fmul_rn(dy, dy)),
                     __fmul_rn(dz, dz));
}

#define INF_F  __int_as_float(0x7f800000)
#define IMAXS  0x7fffffff

// float-key top-3 insert. Candidates arrive with strictly increasing j,
// so strict '<' keeps the smaller index on exact distance ties.
__device__ __forceinline__ void ins3f(float d, int j,
                                      float& d0, int& i0,
                                      float& d1, int& i1,
                                      float& d2, int& i2) {
    if (d < d2) {
        if (d < d1) {
            d2 = d1; i2 = i1;
            if (d < d0) { d1 = d0; i1 = i0; d0 = d; i0 = j; }
            else        { d1 = d;  i1 = j; }
        } else { d2 = d; i2 = j; }
    }
}

// ============================================================
// Kernel 1 (fused): blocks [0, KNN_BLOCKS) do 16-NN (warp/query);
// blocks [KNN_BLOCKS, +FEAT_BLOCKS) do the 3 feature GEMVs + p passthrough.
// (unchanged from R11)
// ============================================================
__global__ void __launch_bounds__(256, 5) prep_kernel(const float* __restrict__ x,
                                                      const float* __restrict__ p,
                                                      const float* __restrict__ Aw,
                                                      const float* __restrict__ Ab,
                                                      const float* __restrict__ Bw,
                                                      const float* __restrict__ Bb,
                                                      const float* __restrict__ Cw,
                                                      const float* __restrict__ Cb,
                                                      float* __restrict__ out) {
    __shared__ __align__(16) float4 sm4[NPTS];   // 32KB
    int tid = threadIdx.x;
    int warp = tid >> 5, lane = tid & 31;

    if (blockIdx.x < KNN_BLOCKS) {
        // ------- KNN branch: warp-per-query, float keys, redux pops -------
        int b = blockIdx.x >> 8;                 // 256 blocks per batch
        int qbase = (blockIdx.x & 255) << 3;     // 8 queries per block
        const float* pb = p + b * NPTS * 3;

        for (int u = tid; u < NPTS; u += 256)
            sm4[u] = make_float4(pb[3*u], pb[3*u+1], pb[3*u+2], 0.0f);
        __syncthreads();

        int qi = qbase + warp;
        float4 q4 = sm4[qi];

        float d0 = INF_F, d1 = INF_F, d2 = INF_F;
        int   i0 = IMAXS, i1 = IMAXS, i2 = IMAXS;
#pragma unroll 4
        for (int t = 0; t < 64; t++) {
            int j = lane + (t << 5);
            float4 c4 = sm4[j];
            float d = sqdist_exact(q4.x - c4.x, q4.y - c4.y, q4.z - c4.z);
            ins3f(d, j, d0, i0, d1, i1, d2, i2);
        }

        unsigned lpd = 0; int lpj = -1;   // last popped (dist bits, idx)
        int myj = 0;                       // this lane's buffered output index

        for (int r = 0; r < KNN + 1; r++) {
            // global min = (min dist bits, then min index among that dist).
            unsigned myd = __float_as_uint(d0);
            unsigned dmin = __reduce_min_sync(0xffffffffu, myd);
            unsigned jc = (myd == dmin) ? (unsigned)i0 : 0xffffffffu;
            unsigned jmin = __reduce_min_sync(0xffffffffu, jc);

            if (lane == r - 1) myj = (int)jmin;  // round 0 == self, dropped

            if (myd == dmin && (unsigned)i0 == jmin) {   // unique winner lane
                lpd = dmin; lpj = (int)jmin;
                d0 = d1; i0 = i1; d1 = d2; i1 = i2; d2 = INF_F; i2 = IMAXS;
                if (i0 == IMAXS) {
                    // refill with 3 smallest keys strictly greater than (lpd,lpj)
                    for (int t = 0; t < 64; t++) {
                        int j = lane + (t << 5);
                        float4 c4 = sm4[j];
                        float d = sqdist_exact(q4.x - c4.x, q4.y - c4.y, q4.z - c4.z);
                        unsigned db = __float_as_uint(d);
                        if (db > lpd || (db == lpd && j > lpj))
                            ins3f(d, j, d0, i0, d1, i1, d2, i2);
                    }
                }
            }
        }
        if (lane < KNN)
            g_idx[(b * NPTS + qi) * KNN + lane] = myj;   // coalesced
    } else {
        // ---------------- FEAT branch: warp-per-point (4 pts/warp) ----------------
        float* sm = (float*)sm4;
        float* sAw = sm;            // 1024
        float* sBw = sm + 1024;     // 1024
        float* sCw = sm + 2048;     // 1024
        float* sAb = sm + 3072;     // 32
        float* sBb = sm + 3104;     // 32
        float* sCb = sm + 3136;     // 32

        for (int u = tid; u < 1024; u += 256) {
            sAw[u] = Aw[u]; sBw[u] = Bw[u]; sCw[u] = Cw[u];
        }
        if (tid < 32) { sAb[tid] = Ab[tid]; sBb[tid] = Bb[tid]; sCb[tid] = Cb[tid]; }
        __syncthreads();

        int fb = blockIdx.x - KNN_BLOCKS;
        int pt0 = fb * 32 + warp * 4;
#pragma unroll
        for (int q = 0; q < 4; q++) {
            int pt = pt0 + q;
            float xv = x[pt * DIM + lane];
            float a = sAb[lane], bb = sBb[lane], cc = sCb[lane];
#pragma unroll
            for (int d = 0; d < 32; d++) {
                float xd = __shfl_sync(0xffffffffu, xv, d);
                a  = fmaf(xd, sAw[d*32 + lane], a);
                bb = fmaf(xd, sBw[d*32 + lane], bb);
                cc = fmaf(xd, sCw[d*32 + lane], cc);
            }
            g_xA[pt*DIM + lane] = a;
            g_xB[pt*DIM + lane] = bb;
            g_xC[pt*DIM + lane] = cc;
        }
        // p passthrough -> second part of output (96 floats per feat block)
        if (tid < 96) out[YOFF + fb*96 + tid] = p[fb*96 + tid];
    }
}

// ============================================================
// Kernel 2: fused gather + position MLP + value MLP + softmax + y.
// 256 threads = 8 points x 16 neighbors x 2 channel-halves.
// Thread (pt, k, half) computes channels [half*16, half*16+16) of its
// pair. hv combined across halves with one shfl_xor(1) add (halves are
// adjacent lanes; commutative, bit-identical on both). Occupancy:
// 4 blocks x 256 = 1024 thr/SM vs 640 before.
// ============================================================
__global__ void __launch_bounds__(256, 4) attn_kernel(const float* __restrict__ p,
                                                      const float* __restrict__ pm1w,
                                                      const float* __restrict__ pm1b,
                                                      const float* __restrict__ pm2w,
                                                      const float* __restrict__ pm2b,
                                                      const float* __restrict__ vm1w,
                                                      const float* __restrict__ vm1b,
                                                      const float* __restrict__ vm2w,
                                                      const float* __restrict__ vm2b,
                                                      float* __restrict__ out) {
    __shared__ __align__(16) float s_pm1w[192];
    __shared__ __align__(16) float s_pm1b[64];
    __shared__ __align__(16) float s_pm2w[2048];
    __shared__ __align__(16) float s_pm2b[32];
    __shared__ __align__(16) float s_vm1t[128];   // transposed: [jj][c]
    __shared__ __align__(16) float s_vm1b[4];
    __shared__ __align__(16) float s_vm2w[128];   // [jj][c]
    __shared__ __align__(16) float s_vm2b[32];
    __shared__ __align__(16) float s_xi[8][32];
    __shared__ __align__(16) float s_h2[8][16][33];
    __shared__ __align__(16) float s_val[8][16][33];

    int tid = threadIdx.x;
    int gp0 = blockIdx.x << 3;

    // ---- load weights + x_i tile (256 threads) ----
    for (int u = tid; u < 2048; u += 256) s_pm2w[u] = pm2w[u];
    if (tid < 192) s_pm1w[tid] = pm1w[tid];
    if (tid < 64)  s_pm1b[tid] = pm1b[tid];
    if (tid < 32)  { s_pm2b[tid] = pm2b[tid]; s_vm2b[tid] = vm2b[tid]; }
    if (tid < 128) {
        int c = tid >> 2, jj = tid & 3;           // vm1w is [c][jj]
        s_vm1t[jj*32 + c] = vm1w[tid];
        s_vm2w[tid] = vm2w[tid];                  // already [jj][c]
    }
    if (tid < 4) s_vm1b[tid] = vm1b[tid];
    {
        int u = tid;
        s_xi[u >> 5][u & 31] = g_xA[(gp0 << 5) + u];
    }
    __syncthreads();

    int half = tid & 1;
    int k = (tid >> 1) & 15;
    int pt = tid >> 5;
    int cbase = half << 4;                 // 0 or 16

    int gp = gp0 + pt;
    int b = gp >> 11, ii = gp & 2047;
    int j = g_idx[(gp << 4) + k];

    const float* pb = p + b * NPTS * 3;
    float dx = pb[ii*3 + 0] - pb[j*3 + 0];
    float dy = pb[ii*3 + 1] - pb[j*3 + 1];
    float dz = pb[ii*3 + 2] - pb[j*3 + 2];

    // ---- posi_diff MLP: 3 -> 64 (relu) -> 32 (this thread: 16 channels) ----
    u64 pd2[8];
#pragma unroll
    for (int i = 0; i < 8; i++)
        pd2[i] = *(const u64*)&s_pm2b[cbase + 2*i];

#pragma unroll
    for (int ch = 0; ch < 4; ch++) {
        float h1c[16];
#pragma unroll
        for (int m = 0; m < 16; m++) {
            int mg = (ch << 4) + m;
            float v = s_pm1b[mg];
            v = fmaf(dx, s_pm1w[mg],       v);
            v = fmaf(dy, s_pm1w[64 + mg],  v);
            v = fmaf(dz, s_pm1w[128 + mg], v);
            h1c[m] = fmaxf(v, 0.0f);
        }
#pragma unroll
        for (int m = 0; m < 16; m++) {
            int mg = (ch << 4) + m;
            u64 hp; PACK2(hp, h1c[m], h1c[m]);
            const ulonglong2* wr = (const ulonglong2*)&s_pm2w[mg * 32 + cbase];
#pragma unroll
            for (int i = 0; i < 4; i++) {
                ulonglong2 w = wr[i];                  // LDS.128 = 2 weight pairs
                FMA2(pd2[2*i],     hp, w.x);
                FMA2(pd2[2*i + 1], hp, w.y);
            }
        }
    }

    // ---- gather this half's neighbor channels; vm1 partials; val -> smem ----
    int row = (b << 11) + j;
    const float4* xb4 = (const float4*)(g_xB + (row << 5) + cbase);
    const float4* xc4 = (const float4*)(g_xC + (row << 5) + cbase);

    u64 acc2[4] = {0ull, 0ull, 0ull, 0ull};
#pragma unroll
    for (int q = 0; q < 4; q++) {
        float4 vb = xb4[q];
        float4 vc = xc4[q];
#pragma unroll
        for (int hh = 0; hh < 2; hh++) {
            int pi = 2*q + hh;
            int c0 = cbase + 2*pi;
            u64 xbp, xcp;
            if (hh == 0) { PACK2(xbp, vb.x, vb.y); PACK2(xcp, vc.x, vc.y); }
            else         { PACK2(xbp, vb.z, vb.w); PACK2(xcp, vc.z, vc.w); }
            u64 xip = *(const u64*)&s_xi[pt][c0];
            u64 t, hpair;
            SUB2(t, xip, xbp);
            ADD2(hpair, t, pd2[pi]);
#pragma unroll
            for (int jj = 0; jj < 4; jj++)
                FMA2(acc2[jj], hpair, *(const u64*)&s_vm1t[jj*32 + c0]);
            u64 valp;
            ADD2(valp, pd2[pi], xcp);
            float vlo, vhi; UNPACK2(vlo, vhi, valp);
            s_val[pt][k][c0]     = vlo;
            s_val[pt][k][c0 + 1] = vhi;
        }
    }

    // hv: combine this half's partial with the other half (adjacent lane).
    float hv[4];
#pragma unroll
    for (int jj = 0; jj < 4; jj++) {
        float lo, hi; UNPACK2(lo, hi, acc2[jj]);
        float part = lo + hi;
        float other = __shfl_xor_sync(0xffffffffu, part, 1);
        hv[jj] = fmaxf(part + other + s_vm1b[jj], 0.0f);
    }

    // ---- vm2: h2 = vm2b + hv @ vm2w  (this thread's 8 c-pairs) ----
    u64 hvp[4];
#pragma unroll
    for (int jj = 0; jj < 4; jj++) PACK2(hvp[jj], hv[jj], hv[jj]);
#pragma unroll
    for (int pi = 0; pi < 8; pi++) {
        int c0 = cbase + 2*pi;
        u64 h2p = *(const u64*)&s_vm2b[c0];
#pragma unroll
        for (int jj = 0; jj < 4; jj++)
            FMA2(h2p, hvp[jj], *(const u64*)&s_vm2w[jj*32 + c0]);
        float hlo, hhi; UNPACK2(hlo, hhi, h2p);
        s_h2[pt][k][c0]     = hlo;
        s_h2[pt][k][c0 + 1] = hhi;
    }
    __syncthreads();

    // ---- softmax over k per (pt, c) + weighted sum: 1 task per thread ----
    {
        int tp = tid >> 5, c = tid & 31;
        float m = s_h2[tp][0][c];
#pragma unroll
        for (int kk = 1; kk < 16; kk++) m = fmaxf(m, s_h2[tp][kk][c]);
        float s = 0.0f, acc = 0.0f;
#pragma unroll
        for (int kk = 0; kk < 16; kk++) {
            float e = __expf(s_h2[tp][kk][c] - m);
            s += e;
            acc = fmaf(e, s_val[tp][kk][c], acc);
        }
        out[((gp0 + tp) << 5) + c] = acc / s;
    }
}

// ============================================================
extern "C" void kernel_launch(void* const* d_in, const int* in_sizes, int n_in,
                              void* d_out, int out_size) {
    const float* x = (const float*)d_in[0];
    const float* p = (const float*)d_in[1];

    prep_kernel<<<KNN_BLOCKS + FEAT_BLOCKS, 256>>>(
        x, p,
        (const float*)d_in[2], (const float*)d_in[3],
        (const float*)d_in[4], (const float*)d_in[5],
        (const float*)d_in[6], (const float*)d_in[7],
        (float*)d_out);

    attn_kernel<<<NTOT/8, 256>>>(
        p,
        (const float*)d_in[8],  (const float*)d_in[9],
        (const float*)d_in[10], (const float*)d_in[11],
        (const float*)d_in[12], (const float*)d_in[13],
        (const float*)d_in[14], (const float*)d_in[15],
        (float*)d_out);
}

// round 15
// speedup vs baseline: 1.1325x; 1.0140x over previous
#include <cuda_runtime.h>

#define BATCH 8
#define NPTS 2048
#define DIM 32
#define KNN 16
#define NTOT (BATCH*NPTS)          /* 16384 */
#define YOFF (NTOT*DIM)            /* 524288 */

#define PREP_PER_BATCH 320         /* 256 knn (8 q/block) + 64 feat */
#define ATTN_PER_BATCH 256
#define PREP_TOTAL (BATCH*PREP_PER_BATCH)   /* 2560 */
#define GRID_TOTAL (PREP_TOTAL + BATCH*ATTN_PER_BATCH)  /* 4608 */

typedef unsigned long long u64;

// -------- scratch (device globals: no allocation allowed) --------
__device__ float g_xA[NTOT*DIM];
__device__ float g_xB[NTOT*DIM];
__device__ float g_xC[NTOT*DIM];
__device__ int   g_idx[NTOT*KNN];
__device__ unsigned g_done[BATCH];   // per-batch prep completion counters

// -------- packed f32x2 helpers (sm_100a PTX) --------
#define PACK2(d, lo, hi) \
    asm("mov.b64 %0, {%1, %2};" : "=l"(d) : "r"(__float_as_uint(lo)), "r"(__float_as_uint(hi)))
#define UNPACK2(lo, hi, s) do { unsigned _ulo, _uhi; \
    asm("mov.b64 {%0, %1}, %2;" : "=r"(_ulo), "=r"(_uhi) : "l"(s)); \
    lo = __uint_as_float(_ulo); hi = __uint_as_float(_uhi); } while(0)
#define FMA2(acc, a, b) \
    asm("fma.rn.f32x2 %0, %1, %2, %0;" : "+l"(acc) : "l"(a), "l"(b))
#define ADD2(d, a, b) \
    asm("add.rn.f32x2 %0, %1, %2;" : "=l"(d) : "l"(a), "l"(b))
#define SUB2(d, a, b) \
    asm("sub.rn.f32x2 %0, %1, %2;" : "=l"(d) : "l"(a), "l"(b))

// Exact (non-FMA-contracted) squared distance, matching XLA's
// mul/mul/mul + sequential-add lowering of sum((pi-pj)**2, -1).
__device__ __forceinline__ float sqdist_exact(float dx, float dy, float dz) {
    return __fadd_rn(__fadd_rn(__fmul_rn(dx, dx), __fmul_rn(dy, dy)),
                     __fmul_rn(dz, dz));
}

#define INF_F  __int_as_float(0x7f800000)
#define IMAXS  0x7fffffff

// float-key top-3 insert. Candidates arrive with strictly increasing j,
// so strict '<' keeps the smaller index on exact distance ties.
__device__ __forceinline__ void ins3f(float d, int j,
                                      float& d0, int& i0,
                                      float& d1, int& i1,
                                      float& d2, int& i2) {
    if (d < d2) {
        if (d < d1) {
            d2 = d1; i2 = i1;
            if (d < d0) { d1 = d0; i1 = i0; d0 = d; i0 = j; }
            else        { d1 = d;  i1 = j; }
        } else { d2 = d; i2 = j; }
    }
}

// attn smem overlay (45,328 B < 48KB static limit)
struct AttnS {
    float pm1w[192];
    float pm1b[64];
    float pm2w[2048];
    float pm2b[32];
    float vm1t[128];   // transposed: [jj][c]
    float vm1b[4];
    float vm2w[128];   // [jj][c]
    float vm2b[32];
    float xi[8][32];
    float h2[8][16][33];
    float val[8][16][33];
};

// ============================================================
// reset counters (graph node 1)
// ============================================================
__global__ void reset_kernel() {
    if (threadIdx.x < BATCH) g_done[threadIdx.x] = 0;
}

// ============================================================
// Fused kernel: blocks [0, PREP_TOTAL) = prep (batch-major:
// per batch 256 knn-blocks then 64 feat-blocks), arriving on
// g_done[b]; blocks [PREP_TOTAL, GRID_TOTAL) = attn, spinning
// until g_done[b] == PREP_PER_BATCH.
// ============================================================
__global__ void __launch_bounds__(256, 4) fused_kernel(
        const float* __restrict__ x,
        const float* __restrict__ p,
        const float* __restrict__ Aw,  const float* __restrict__ Ab,
        const float* __restrict__ Bw,  const float* __restrict__ Bb,
        const float* __restrict__ Cw,  const float* __restrict__ Cb,
        const float* __restrict__ pm1w, const float* __restrict__ pm1b,
        const float* __restrict__ pm2w, const float* __restrict__ pm2b,
        const float* __restrict__ vm1w, const float* __restrict__ vm1b,
        const float* __restrict__ vm2w, const float* __restrict__ vm2b,
        float* __restrict__ out) {
    __shared__ __align__(16) char smem_raw[sizeof(AttnS)];
    int tid = threadIdx.x;
    int warp = tid >> 5, lane = tid & 31;

    if (blockIdx.x < PREP_TOTAL) {
        // ================= PREP =================
        int b  = blockIdx.x / PREP_PER_BATCH;
        int rb = blockIdx.x - b * PREP_PER_BATCH;

        if (rb < 256) {
            // ------- KNN: warp-per-query, float keys, redux pops -------
            float4* sm4 = reinterpret_cast<float4*>(smem_raw);
            int qbase = rb << 3;                     // 8 queries per block
            const float* pb = p + b * NPTS * 3;

            for (int u = tid; u < NPTS; u += 256)
                sm4[u] = make_float4(pb[3*u], pb[3*u+1], pb[3*u+2], 0.0f);
            __syncthreads();

            int qi = qbase + warp;
            float4 q4 = sm4[qi];

            float d0 = INF_F, d1 = INF_F, d2 = INF_F;
            int   i0 = IMAXS, i1 = IMAXS, i2 = IMAXS;
#pragma unroll 4
            for (int t = 0; t < 64; t++) {
                int j = lane + (t << 5);
                float4 c4 = sm4[j];
                float d = sqdist_exact(q4.x - c4.x, q4.y - c4.y, q4.z - c4.z);
                ins3f(d, j, d0, i0, d1, i1, d2, i2);
            }

            unsigned lpd = 0; int lpj = -1;
            int myj = 0;

            for (int r = 0; r < KNN + 1; r++) {
                unsigned myd = __float_as_uint(d0);
                unsigned dmin = __reduce_min_sync(0xffffffffu, myd);
                unsigned jc = (myd == dmin) ? (unsigned)i0 : 0xffffffffu;
                unsigned jmin = __reduce_min_sync(0xffffffffu, jc);

                if (lane == r - 1) myj = (int)jmin;  // round 0 == self, dropped

                if (myd == dmin && (unsigned)i0 == jmin) {   // unique winner
                    lpd = dmin; lpj = (int)jmin;
                    d0 = d1; i0 = i1; d1 = d2; i1 = i2; d2 = INF_F; i2 = IMAXS;
                    if (i0 == IMAXS) {
                        for (int t = 0; t < 64; t++) {
                            int j = lane + (t << 5);
                            float4 c4 = sm4[j];
                            float d = sqdist_exact(q4.x - c4.x, q4.y - c4.y, q4.z - c4.z);
                            unsigned db = __float_as_uint(d);
                            if (db > lpd || (db == lpd && j > lpj))
                                ins3f(d, j, d0, i0, d1, i1, d2, i2);
                        }
                    }
                }
            }
            if (lane < KNN)
                g_idx[(b * NPTS + qi) * KNN + lane] = myj;   // coalesced
        } else {
            // ------- FEAT: warp-per-point (4 pts/warp) -------
            float* sm = reinterpret_cast<float*>(smem_raw);
            float* sAw = sm;            // 1024
            float* sBw = sm + 1024;     // 1024
            float* sCw = sm + 2048;     // 1024
            float* sAb = sm + 3072;     // 32
            float* sBb = sm + 3104;     // 32
            float* sCb = sm + 3136;     // 32

            for (int u = tid; u < 1024; u += 256) {
                sAw[u] = Aw[u]; sBw[u] = Bw[u]; sCw[u] = Cw[u];
            }
            if (tid < 32) { sAb[tid] = Ab[tid]; sBb[tid] = Bb[tid]; sCb[tid] = Cb[tid]; }
            __syncthreads();

            int fbg = b * 64 + (rb - 256);             // global feat block
            int pt0 = fbg * 32 + warp * 4;
#pragma unroll
            for (int q = 0; q < 4; q++) {
                int pt = pt0 + q;
                float xv = x[pt * DIM + lane];
                float a = sAb[lane], bb = sBb[lane], cc = sCb[lane];
#pragma unroll
                for (int d = 0; d < 32; d++) {
                    float xd = __shfl_sync(0xffffffffu, xv, d);
                    a  = fmaf(xd, sAw[d*32 + lane], a);
                    bb = fmaf(xd, sBw[d*32 + lane], bb);
                    cc = fmaf(xd, sCw[d*32 + lane], cc);
                }
                g_xA[pt*DIM + lane] = a;
                g_xB[pt*DIM + lane] = bb;
                g_xC[pt*DIM + lane] = cc;
            }
            // p passthrough -> second part of output
            if (tid < 96) out[YOFF + fbg*96 + tid] = p[fbg*96 + tid];
        }

        // release: all writes, then count this block done
        __threadfence();
        __syncthreads();
        if (tid == 0) atomicAdd(&g_done[b], 1u);
    } else {
        // ================= ATTN =================
        AttnS* A = reinterpret_cast<AttnS*>(smem_raw);
        int aidx = blockIdx.x - PREP_TOTAL;
        int b = aidx >> 8;
        int gp0 = aidx << 3;                     // == (b<<11) + (local<<3)

        // ---- load weights (independent of prep) ----
        for (int u = tid; u < 2048; u += 256) A->pm2w[u] = pm2w[u];
        if (tid < 192) A->pm1w[tid] = pm1w[tid];
        if (tid < 64)  A->pm1b[tid] = pm1b[tid];
        if (tid < 32)  { A->pm2b[tid] = pm2b[tid]; A->vm2b[tid] = vm2b[tid]; }
        if (tid < 128) {
            int c = tid >> 2, jj = tid & 3;           // vm1w is [c][jj]
            A->vm1t[jj*32 + c] = vm1w[tid];
            A->vm2w[tid] = vm2w[tid];                 // already [jj][c]
        }
        if (tid < 4) A->vm1b[tid] = vm1b[tid];

        // ---- wait for this batch's prep (leader acquire + bar) ----
        if (tid == 0) {
            unsigned v;
            for (;;) {
                asm volatile("ld.acquire.gpu.u32 %0, [%1];"
                             : "=r"(v) : "l"(&g_done[b]) : "memory");
                if (v >= PREP_PER_BATCH) break;
                __nanosleep(200);
            }
        }
        __syncthreads();

        // ---- x_i tile (depends on prep) ----
        {
            int u = tid;
            A->xi[u >> 5][u & 31] = g_xA[(gp0 << 5) + u];
        }
        __syncthreads();

        int half = tid & 1;
        int k = (tid >> 1) & 15;
        int pt = tid >> 5;
        int cbase = half << 4;                 // 0 or 16

        int gp = gp0 + pt;
        int ii = gp & 2047;
        int j = g_idx[(gp << 4) + k];

        const float* pb = p + b * NPTS * 3;
        float dx = pb[ii*3 + 0] - pb[j*3 + 0];
        float dy = pb[ii*3 + 1] - pb[j*3 + 1];
        float dz = pb[ii*3 + 2] - pb[j*3 + 2];

        // ---- posi_diff MLP: 3 -> 64 (relu) -> 32 (16 channels here) ----
        u64 pd2[8];
#pragma unroll
        for (int i = 0; i < 8; i++)
            pd2[i] = *(const u64*)&A->pm2b[cbase + 2*i];

#pragma unroll
        for (int ch = 0; ch < 4; ch++) {
            float h1c[16];
#pragma unroll
            for (int m = 0; m < 16; m++) {
                int mg = (ch << 4) + m;
                float v = A->pm1b[mg];
                v = fmaf(dx, A->pm1w[mg],       v);
                v = fmaf(dy, A->pm1w[64 + mg],  v);
                v = fmaf(dz, A->pm1w[128 + mg], v);
                h1c[m] = fmaxf(v, 0.0f);
            }
#pragma unroll
            for (int m = 0; m < 16; m++) {
                int mg = (ch << 4) + m;
                u64 hp; PACK2(hp, h1c[m], h1c[m]);
                const ulonglong2* wr = (const ulonglong2*)&A->pm2w[mg * 32 + cbase];
#pragma unroll
                for (int i = 0; i < 4; i++) {
                    ulonglong2 w = wr[i];              // LDS.128 = 2 weight pairs
                    FMA2(pd2[2*i],     hp, w.x);
                    FMA2(pd2[2*i + 1], hp, w.y);
                }
            }
        }

        // ---- gather this half's channels; vm1 partials; val -> smem ----
        int row = (b << 11) + j;
        const float4* xb4 = (const float4*)(g_xB + (row << 5) + cbase);
        const float4* xc4 = (const float4*)(g_xC + (row << 5) + cbase);

        u64 acc2[4] = {0ull, 0ull, 0ull, 0ull};
#pragma unroll
        for (int q = 0; q < 4; q++) {
            float4 vb = xb4[q];
            float4 vc = xc4[q];
#pragma unroll
            for (int hh = 0; hh < 2; hh++) {
                int pi = 2*q + hh;
                int c0 = cbase + 2*pi;
                u64 xbp, xcp;
                if (hh == 0) { PACK2(xbp, vb.x, vb.y); PACK2(xcp, vc.x, vc.y); }
                else         { PACK2(xbp, vb.z, vb.w); PACK2(xcp, vc.z, vc.w); }
                u64 xip = *(const u64*)&A->xi[pt][c0];
                u64 t, hpair;
                SUB2(t, xip, xbp);
                ADD2(hpair, t, pd2[pi]);
#pragma unroll
                for (int jj = 0; jj < 4; jj++)
                    FMA2(acc2[jj], hpair, *(const u64*)&A->vm1t[jj*32 + c0]);
                u64 valp;
                ADD2(valp, pd2[pi], xcp);
                float vlo, vhi; UNPACK2(vlo, vhi, valp);
                A->val[pt][k][c0]     = vlo;
                A->val[pt][k][c0 + 1] = vhi;
            }
        }

        // hv: combine with the other half (adjacent lane).
        float hv[4];
#pragma unroll
        for (int jj = 0; jj < 4; jj++) {
            float lo, hi; UNPACK2(lo, hi, acc2[jj]);
            float part = lo + hi;
            float other = __shfl_xor_sync(0xffffffffu, part, 1);
            hv[jj] = fmaxf(part + other + A->vm1b[jj], 0.0f);
        }

        // ---- vm2: h2 = vm2b + hv @ vm2w ----
        u64 hvp[4];
#pragma unroll
        for (int jj = 0; jj < 4; jj++) PACK2(hvp[jj], hv[jj], hv[jj]);
#pragma unroll
        for (int pi = 0; pi < 8; pi++) {
            int c0 = cbase + 2*pi;
            u64 h2p = *(const u64*)&A->vm2b[c0];
#pragma unroll
            for (int jj = 0; jj < 4; jj++)
                FMA2(h2p, hvp[jj], *(const u64*)&A->vm2w[jj*32 + c0]);
            float hlo, hhi; UNPACK2(hlo, hhi, h2p);
            A->h2[pt][k][c0]     = hlo;
            A->h2[pt][k][c0 + 1] = hhi;
        }
        __syncthreads();

        // ---- softmax over k per (pt, c) + weighted sum ----
        {
            int tp = tid >> 5, c = tid & 31;
            float m = A->h2[tp][0][c];
#pragma unroll
            for (int kk = 1; kk < 16; kk++) m = fmaxf(m, A->h2[tp][kk][c]);
            float s = 0.0f, acc = 0.0f;
#pragma unroll
            for (int kk = 0; kk < 16; kk++) {
                float e = __expf(A->h2[tp][kk][c] - m);
                s += e;
                acc = fmaf(e, A->val[tp][kk][c], acc);
            }
            out[((gp0 + tp) << 5) + c] = acc / s;
        }
    }
}

// ============================================================
extern "C" void kernel_launch(void* const* d_in, const int* in_sizes, int n_in,
                              void* d_out, int out_size) {
    const float* x = (const float*)d_in[0];
    const float* p = (const float*)d_in[1];

    reset_kernel<<<1, 32>>>();
    fused_kernel<<<GRID_TOTAL, 256>>>(
        x, p,
        (const float*)d_in[2],  (const float*)d_in[3],
        (const float*)d_in[4],  (const float*)d_in[5],
        (const float*)d_in[6],  (const float*)d_in[7],
        (const float*)d_in[8],  (const float*)d_in[9],
        (const float*)d_in[10], (const float*)d_in[11],
        (const float*)d_in[12], (const float*)d_in[13],
        (const float*)d_in[14], (const float*)d_in[15],
        (float*)d_out);
}

// round 17
// speedup vs baseline: 1.2209x; 1.0781x over previous
#include <cuda_runtime.h>

#define BATCH 8
#define NPTS 2048
#define DIM 32
#define KNN 16
#define NTOT (BATCH*NPTS)          /* 16384 */
#define YOFF (NTOT*DIM)            /* 524288 */

#define PREP_PER_BATCH 320         /* 256 knn (8 q/block) + 64 feat */
#define ATTN_PER_BATCH 256
#define PREP_TOTAL (BATCH*PREP_PER_BATCH)   /* 2560 */
#define GRID_TOTAL (PREP_TOTAL + BATCH*ATTN_PER_BATCH)  /* 4608 */

typedef unsigned long long u64;

// -------- scratch (device globals: no allocation allowed) --------
__device__ float g_xA[NTOT*DIM];
__device__ float g_xB[NTOT*DIM];
__device__ float g_xC[NTOT*DIM];
__device__ int   g_idx[NTOT*KNN];
__device__ unsigned g_done[BATCH];   // per-batch prep completion counters

// -------- packed f32x2 helpers (sm_100a PTX) --------
#define PACK2(d, lo, hi) \
    asm("mov.b64 %0, {%1, %2};" : "=l"(d) : "r"(__float_as_uint(lo)), "r"(__float_as_uint(hi)))
#define UNPACK2(lo, hi, s) do { unsigned _ulo, _uhi; \
    asm("mov.b64 {%0, %1}, %2;" : "=r"(_ulo), "=r"(_uhi) : "l"(s)); \
    lo = __uint_as_float(_ulo); hi = __uint_as_float(_uhi); } while(0)
#define FMA2(acc, a, b) \
    asm("fma.rn.f32x2 %0, %1, %2, %0;" : "+l"(acc) : "l"(a), "l"(b))
#define ADD2(d, a, b) \
    asm("add.rn.f32x2 %0, %1, %2;" : "=l"(d) : "l"(a), "l"(b))
#define SUB2(d, a, b) \
    asm("sub.rn.f32x2 %0, %1, %2;" : "=l"(d) : "l"(a), "l"(b))
#define MUL2(d, a, b) \
    asm("mul.rn.f32x2 %0, %1, %2;" : "=l"(d) : "l"(a), "l"(b))

// Exact (non-FMA-contracted) squared distance, matching XLA's
// mul/mul/mul + sequential-add lowering of sum((pi-pj)**2, -1).
__device__ __forceinline__ float sqdist_exact(float dx, float dy, float dz) {
    return __fadd_rn(__fadd_rn(__fmul_rn(dx, dx), __fmul_rn(dy, dy)),
                     __fmul_rn(dz, dz));
}

// Packed 2-candidate squared terms (sub+mul only — NO packed adds:
// ptxas fuses mul.rn.f32x2+add.rn.f32x2 into FFMA2, which changed the
// distance bits in R16 and flipped KNN near-ties. Scalar __fadd_rn
// finishers below reproduce the exact scalar sequence per candidate.)
__device__ __forceinline__ void sqterms2(u64 qx2, u64 qy2, u64 qz2,
                                         u64 cx2, u64 cy2, u64 cz2,
                                         u64& mx, u64& my, u64& mz) {
    u64 dx2, dy2, dz2;
    SUB2(dx2, qx2, cx2); SUB2(dy2, qy2, cy2); SUB2(dz2, qz2, cz2);
    MUL2(mx, dx2, dx2);  MUL2(my, dy2, dy2);  MUL2(mz, dz2, dz2);
}

#define INF_F  __int_as_float(0x7f800000)
#define IMAXS  0x7fffffff

// float-key top-3 insert. Candidates arrive with strictly increasing j,
// so strict '<' keeps the smaller index on exact distance ties.
__device__ __forceinline__ void ins3f(float d, int j,
                                      float& d0, int& i0,
                                      float& d1, int& i1,
                                      float& d2, int& i2) {
    if (d < d2) {
        if (d < d1) {
            d2 = d1; i2 = i1;
            if (d < d0) { d1 = d0; i1 = i0; d0 = d; i0 = j; }
            else        { d1 = d;  i1 = j; }
        } else { d2 = d; i2 = j; }
    }
}

// attn smem overlay (45,328 B < 48KB static limit)
struct AttnS {
    float pm1w[192];
    float pm1b[64];
    float pm2w[2048];
    float pm2b[32];
    float vm1t[128];   // transposed: [jj][c]
    float vm1b[4];
    float vm2w[128];   // [jj][c]
    float vm2b[32];
    float xi[8][32];
    float h2[8][16][33];
    float val[8][16][33];
};

// ============================================================
// reset counters (graph node 1)
// ============================================================
__global__ void reset_kernel() {
    if (threadIdx.x < BATCH) g_done[threadIdx.x] = 0;
}

// ============================================================
// Fused kernel: blocks [0, PREP_TOTAL) = prep (batch-major:
// per batch 256 knn-blocks then 64 feat-blocks), arriving on
// g_done[b]; blocks [PREP_TOTAL, GRID_TOTAL) = attn, spinning
// until g_done[b] == PREP_PER_BATCH.
// ============================================================
__global__ void __launch_bounds__(256, 4) fused_kernel(
        const float* __restrict__ x,
        const float* __restrict__ p,
        const float* __restrict__ Aw,  const float* __restrict__ Ab,
        const float* __restrict__ Bw,  const float* __restrict__ Bb,
        const float* __restrict__ Cw,  const float* __restrict__ Cb,
        const float* __restrict__ pm1w, const float* __restrict__ pm1b,
        const float* __restrict__ pm2w, const float* __restrict__ pm2b,
        const float* __restrict__ vm1w, const float* __restrict__ vm1b,
        const float* __restrict__ vm2w, const float* __restrict__ vm2b,
        float* __restrict__ out) {
    __shared__ __align__(16) char smem_raw[sizeof(AttnS)];
    int tid = threadIdx.x;
    int warp = tid >> 5, lane = tid & 31;

    if (blockIdx.x < PREP_TOTAL) {
        // ================= PREP =================
        int b  = blockIdx.x / PREP_PER_BATCH;
        int rb = blockIdx.x - b * PREP_PER_BATCH;

        if (rb < 256) {
            // ------- KNN: warp-per-query, paired sub/mul + scalar adds -------
            float* smx = reinterpret_cast<float*>(smem_raw);   // 2048
            float* smy = smx + NPTS;                           // 2048
            float* smz = smy + NPTS;                           // 2048
            int qbase = rb << 3;                     // 8 queries per block
            const float* pb = p + b * NPTS * 3;

            for (int u = tid; u < NPTS; u += 256) {
                smx[u] = pb[3*u];
                smy[u] = pb[3*u + 1];
                smz[u] = pb[3*u + 2];
            }
            __syncthreads();

            int qi = qbase + warp;
            float qx = smx[qi], qy = smy[qi], qz = smz[qi];
            u64 qx2, qy2, qz2;
            PACK2(qx2, qx, qx); PACK2(qy2, qy, qy); PACK2(qz2, qz, qz);

            float d0 = INF_F, d1 = INF_F, d2 = INF_F;
            int   i0 = IMAXS, i1 = IMAXS, i2 = IMAXS;
#pragma unroll 4
            for (int t = 0; t < 32; t++) {
                int u = lane + (t << 5);            // candidate pair (2u, 2u+1)
                u64 cx2 = *(const u64*)&smx[2*u];
                u64 cy2 = *(const u64*)&smy[2*u];
                u64 cz2 = *(const u64*)&smz[2*u];
                u64 mx, my, mz;
                sqterms2(qx2, qy2, qz2, cx2, cy2, cz2, mx, my, mz);
                float sxa, sxb, sya, syb, sza, szb;
                UNPACK2(sxa, sxb, mx); UNPACK2(sya, syb, my); UNPACK2(sza, szb, mz);
                float da = __fadd_rn(__fadd_rn(sxa, sya), sza);
                float db = __fadd_rn(__fadd_rn(sxb, syb), szb);
                ins3f(da, 2*u,     d0, i0, d1, i1, d2, i2);
                ins3f(db, 2*u + 1, d0, i0, d1, i1, d2, i2);
            }

            unsigned lpd = 0; int lpj = -1;
            int myj = 0;

            for (int r = 0; r < KNN + 1; r++) {
                unsigned myd = __float_as_uint(d0);
                unsigned dmin = __reduce_min_sync(0xffffffffu, myd);
                unsigned jc = (myd == dmin) ? (unsigned)i0 : 0xffffffffu;
                unsigned jmin = __reduce_min_sync(0xffffffffu, jc);

                if (lane == r - 1) myj = (int)jmin;  // round 0 == self, dropped

                if (myd == dmin && (unsigned)i0 == jmin) {   // unique winner
                    lpd = dmin; lpj = (int)jmin;
                    d0 = d1; i0 = i1; d1 = d2; i1 = i2; d2 = INF_F; i2 = IMAXS;
                    if (i0 == IMAXS) {
                        // refill: 3 smallest keys strictly greater than (lpd,lpj)
                        for (int t = 0; t < 32; t++) {
                            int u = lane + (t << 5);
                            u64 cx2 = *(const u64*)&smx[2*u];
                            u64 cy2 = *(const u64*)&smy[2*u];
                            u64 cz2 = *(const u64*)&smz[2*u];
                            u64 mx, my, mz;
                            sqterms2(qx2, qy2, qz2, cx2, cy2, cz2, mx, my, mz);
                            float sxa, sxb, sya, syb, sza, szb;
                            UNPACK2(sxa, sxb, mx); UNPACK2(sya, syb, my); UNPACK2(sza, szb, mz);
                            float da = __fadd_rn(__fadd_rn(sxa, sya), sza);
                            float db = __fadd_rn(__fadd_rn(sxb, syb), szb);
                            unsigned dba = __float_as_uint(da);
                            unsigned dbb = __float_as_uint(db);
                            if (dba > lpd || (dba == lpd && 2*u > lpj))
                                ins3f(da, 2*u, d0, i0, d1, i1, d2, i2);
                            if (dbb > lpd || (dbb == lpd && 2*u + 1 > lpj))
                                ins3f(db, 2*u + 1, d0, i0, d1, i1, d2, i2);
                        }
                    }
                }
            }
            if (lane < KNN)
                g_idx[(b * NPTS + qi) * KNN + lane] = myj;   // coalesced
        } else {
            // ------- FEAT: warp-per-point (4 pts/warp) -------
            float* sm = reinterpret_cast<float*>(smem_raw);
            float* sAw = sm;            // 1024
            float* sBw = sm + 1024;     // 1024
            float* sCw = sm + 2048;     // 1024
            float* sAb = sm + 3072;     // 32
            float* sBb = sm + 3104;     // 32
            float* sCb = sm + 3136;     // 32

            for (int u = tid; u < 1024; u += 256) {
                sAw[u] = Aw[u]; sBw[u] = Bw[u]; sCw[u] = Cw[u];
            }
            if (tid < 32) { sAb[tid] = Ab[tid]; sBb[tid] = Bb[tid]; sCb[tid] = Cb[tid]; }
            __syncthreads();

            int fbg = b * 64 + (rb - 256);             // global feat block
            int pt0 = fbg * 32 + warp * 4;
#pragma unroll
            for (int q = 0; q < 4; q++) {
                int pt = pt0 + q;
                float xv = x[pt * DIM + lane];
                float a = sAb[lane], bb = sBb[lane], cc = sCb[lane];
#pragma unroll
                for (int d = 0; d < 32; d++) {
                    float xd = __shfl_sync(0xffffffffu, xv, d);
                    a  = fmaf(xd, sAw[d*32 + lane], a);
                    bb = fmaf(xd, sBw[d*32 + lane], bb);
                    cc = fmaf(xd, sCw[d*32 + lane], cc);
                }
                g_xA[pt*DIM + lane] = a;
                g_xB[pt*DIM + lane] = bb;
                g_xC[pt*DIM + lane] = cc;
            }
            // p passthrough -> second part of output
            if (tid < 96) out[YOFF + fbg*96 + tid] = p[fbg*96 + tid];
        }

        // release: all writes, then count this block done
        __threadfence();
        __syncthreads();
        if (tid == 0) atomicAdd(&g_done[b], 1u);
    } else {
        // ================= ATTN =================
        AttnS* A = reinterpret_cast<AttnS*>(smem_raw);
        int aidx = blockIdx.x - PREP_TOTAL;
        int b = aidx >> 8;
        int gp0 = aidx << 3;                     // == (b<<11) + (local<<3)

        // ---- load weights (independent of prep) ----
        for (int u = tid; u < 2048; u += 256) A->pm2w[u] = pm2w[u];
        if (tid < 192) A->pm1w[tid] = pm1w[tid];
        if (tid < 64)  A->pm1b[tid] = pm1b[tid];
        if (tid < 32)  { A->pm2b[tid] = pm2b[tid]; A->vm2b[tid] = vm2b[tid]; }
        if (tid < 128) {
            int c = tid >> 2, jj = tid & 3;           // vm1w is [c][jj]
            A->vm1t[jj*32 + c] = vm1w[tid];
            A->vm2w[tid] = vm2w[tid];                 // already [jj][c]
        }
        if (tid < 4) A->vm1b[tid] = vm1b[tid];

        // ---- wait for this batch's prep (leader acquire + bar) ----
        if (tid == 0) {
            unsigned v;
            for (;;) {
                asm volatile("ld.acquire.gpu.u32 %0, [%1];"
                             : "=r"(v) : "l"(&g_done[b]) : "memory");
                if (v >= PREP_PER_BATCH) break;
                __nanosleep(1000);
            }
        }
        __syncthreads();

        // ---- x_i tile (depends on prep) ----
        {
            int u = tid;
            A->xi[u >> 5][u & 31] = g_xA[(gp0 << 5) + u];
        }
        __syncthreads();

        int half = tid & 1;
        int k = (tid >> 1) & 15;
        int pt = tid >> 5;
        int cbase = half << 4;                 // 0 or 16

        int gp = gp0 + pt;
        int ii = gp & 2047;
        int j = g_idx[(gp << 4) + k];

        const float* pb = p + b * NPTS * 3;
        float dx = pb[ii*3 + 0] - pb[j*3 + 0];
        float dy = pb[ii*3 + 1] - pb[j*3 + 1];
        float dz = pb[ii*3 + 2] - pb[j*3 + 2];

        // ---- posi_diff MLP: 3 -> 64 (relu) -> 32 (16 channels here) ----
        u64 pd2[8];
#pragma unroll
        for (int i = 0; i < 8; i++)
            pd2[i] = *(const u64*)&A->pm2b[cbase + 2*i];

#pragma unroll
        for (int ch = 0; ch < 4; ch++) {
            float h1c[16];
#pragma unroll
            for (int m = 0; m < 16; m++) {
                int mg = (ch << 4) + m;
                float v = A->pm1b[mg];
                v = fmaf(dx, A->pm1w[mg],       v);
                v = fmaf(dy, A->pm1w[64 + mg],  v);
                v = fmaf(dz, A->pm1w[128 + mg], v);
                h1c[m] = fmaxf(v, 0.0f);
            }
#pragma unroll
            for (int m = 0; m < 16; m++) {
                int mg = (ch << 4) + m;
                u64 hp; PACK2(hp, h1c[m], h1c[m]);
                const ulonglong2* wr = (const ulonglong2*)&A->pm2w[mg * 32 + cbase];
#pragma unroll
                for (int i = 0; i < 4; i++) {
                    ulonglong2 w = wr[i];              // LDS.128 = 2 weight pairs
                    FMA2(pd2[2*i],     hp, w.x);
                    FMA2(pd2[2*i + 1], hp, w.y);
                }
            }
        }

        // ---- gather this half's channels; vm1 partials; val -> smem ----
        int row = (b << 11) + j;
        const float4* xb4 = (const float4*)(g_xB + (row << 5) + cbase);
        const float4* xc4 = (const float4*)(g_xC + (row << 5) + cbase);

        u64 acc2[4] = {0ull, 0ull, 0ull, 0ull};
#pragma unroll
        for (int q = 0; q < 4; q++) {
            float4 vb = xb4[q];
            float4 vc = xc4[q];
#pragma unroll
            for (int hh = 0; hh < 2; hh++) {
                int pi = 2*q + hh;
                int c0 = cbase + 2*pi;
                u64 xbp, xcp;
                if (hh == 0) { PACK2(xbp, vb.x, vb.y); PACK2(xcp, vc.x, vc.y); }
                else         { PACK2(xbp, vb.z, vb.w); PACK2(xcp, vc.z, vc.w); }
                u64 xip = *(const u64*)&A->xi[pt][c0];
                u64 t, hpair;
                SUB2(t, xip, xbp);
                ADD2(hpair, t, pd2[pi]);
#pragma unroll
                for (int jj = 0; jj < 4; jj++)
                    FMA2(acc2[jj], hpair, *(const u64*)&A->vm1t[jj*32 + c0]);
                u64 valp;
                ADD2(valp, pd2[pi], xcp);
                float vlo, vhi; UNPACK2(vlo, vhi, valp);
                A->val[pt][k][c0]     = vlo;
                A->val[pt][k][c0 + 1] = vhi;
            }
        }

        // hv: combine with the other half (adjacent lane).
        float hv[4];
#pragma unroll
        for (int jj = 0; jj < 4; jj++) {
            float lo, hi; UNPACK2(lo, hi, acc2[jj]);
            float part = lo + hi;
            float other = __shfl_xor_sync(0xffffffffu, part, 1);
            hv[jj] = fmaxf(part + other + A->vm1b[jj], 0.0f);
        }

        // ---- vm2: h2 = vm2b + hv @ vm2w ----
        u64 hvp[4];
#pragma unroll
        for (int jj = 0; jj < 4; jj++) PACK2(hvp[jj], hv[jj], hv[jj]);
#pragma unroll
        for (int pi = 0; pi < 8; pi++) {
            int c0 = cbase + 2*pi;
            u64 h2p = *(const u64*)&A->vm2b[c0];
#pragma unroll
            for (int jj = 0; jj < 4; jj++)
                FMA2(h2p, hvp[jj], *(const u64*)&A->vm2w[jj*32 + c0]);
            float hlo, hhi; UNPACK2(hlo, hhi, h2p);
            A->h2[pt][k][c0]     = hlo;
            A->h2[pt][k][c0 + 1] = hhi;
        }
        __syncthreads();

        // ---- softmax over k per (pt, c) + weighted sum ----
        {
            int tp = tid >> 5, c = tid & 31;
            float m = A->h2[tp][0][c];
#pragma unroll
            for (int kk = 1; kk < 16; kk++) m = fmaxf(m, A->h2[tp][kk][c]);
            float s = 0.0f, acc = 0.0f;
#pragma unroll
            for (int kk = 0; kk < 16; kk++) {
                float e = __expf(A->h2[tp][kk][c] - m);
                s += e;
                acc = fmaf(e, A->val[tp][kk][c], acc);
            }
            out[((gp0 + tp) << 5) + c] = acc / s;
        }
    }
}

// ============================================================
extern "C" void kernel_launch(void* const* d_in, const int* in_sizes, int n_in,
                              void* d_out, int out_size) {
    const float* x = (const float*)d_in[0];
    const float* p = (const float*)d_in[1];

    reset_kernel<<<1, 32>>>();
    fused_kernel<<<GRID_TOTAL, 256>>>(
        x, p,
        (const float*)d_in[2],  (const float*)d_in[3],
        (const float*)d_in[4],  (const float*)d_in[5],
        (const float*)d_in[6],  (const float*)d_in[7],
        (const float*)d_in[8],  (const float*)d_in[9],
        (const float*)d_in[10], (const float*)d_in[11],
        (const float*)d_in[12], (const float*)d_in[13],
        (const float*)d_in[14], (const float*)d_in[15],
        (float*)d_out);
}